// round 5
// baseline (speedup 1.0000x reference)
#include <cuda_runtime.h>
#include <cstdint>

#define BB 256
#define TT 199
#define QQ 1000
#define NROW (BB * TT)                // 50,944
#define NEL  ((size_t)NROW * QQ)      // 50,944,000

// Scratch (__device__ globals; zero at load; last block resets them so every
// graph replay starts from zero).
__device__ double       g_bsum[BB];
__device__ int          g_bcnt[BB];
__device__ unsigned int g_ticket;

// One block per (b, t) row of 1000 elements. R2-proven body + fused finalize.
__global__ __launch_bounds__(256) void row_kernel(
    const float* __restrict__ pred,    // (B, T, Q)
    const float* __restrict__ batch,   // (B, T+1, Q)
    float* __restrict__ out)
{
    const int t   = blockIdx.x;
    const int b   = blockIdx.y;
    const int tid = threadIdx.x;
    const int lane = tid & 31;
    const int wid  = tid >> 5;

    const size_t row = (size_t)b * TT + t;
    const float* __restrict__ gt_row = batch + ((size_t)b * (TT + 1) + (t + 1)) * QQ;
    const float* __restrict__ p_row  = pred + row * QQ;

    __shared__ int    s_w[8];
    __shared__ float  s_red[8];
    __shared__ int    s_last;
    __shared__ double s_d[BB];

    // ---- all 8 loads up front, unconditionally (max MLP) ----
    float g[4], p[4];
    #pragma unroll
    for (int k = 0; k < 4; k++) {
        int q = tid + 256 * k;
        bool valid = (k < 3) || (tid < QQ - 768);
        g[k] = valid ? gt_row[q] : 0.0f;
        p[k] = valid ? p_row[q]  : 0.0f;
    }

    // ---- block-wide any(g == 1) ----
    int anyv = (g[0] == 1.0f) | (g[1] == 1.0f) | (g[2] == 1.0f) | (g[3] == 1.0f);
    unsigned wany = __ballot_sync(0xFFFFFFFFu, anyv);
    if (lane == 0) s_w[wid] = (wany != 0);
    __syncthreads();
    const int masked = s_w[0] | s_w[1] | s_w[2] | s_w[3] |
                       s_w[4] | s_w[5] | s_w[6] | s_w[7];

    float* __restrict__ out_pred = out + 1 + row * QQ;
    float* __restrict__ out_gt   = out + 1 + NEL + row * QQ;

    float lsum = 0.0f;   // +(g log p + (1-g) log(1-p)); bce = -lsum
    if (masked) {
        #pragma unroll
        for (int k = 0; k < 4; k++) {
            int q = tid + 256 * k;
            bool valid = (k < 3) || (tid < QQ - 768);
            float pp = p[k], gg = g[k];
            float lp = fmaxf(__logf(pp),        -100.0f);
            float l1 = fmaxf(__logf(1.0f - pp), -100.0f);
            lsum += gg * lp + (1.0f - gg) * l1;
            if (valid) {
                out_pred[q] = pp;
                out_gt[q]   = gg;
            }
        }
    } else {
        #pragma unroll
        for (int k = 0; k < 4; k++) {
            int q = tid + 256 * k;
            bool valid = (k < 3) || (tid < QQ - 768);
            if (valid) {
                out_pred[q] = 0.0f;
                out_gt[q]   = 0.0f;
            }
        }
    }

    // ---- block reduction of lsum ----
    #pragma unroll
    for (int off = 16; off > 0; off >>= 1)
        lsum += __shfl_down_sync(0xFFFFFFFFu, lsum, off);
    if (lane == 0) s_red[wid] = lsum;
    __syncthreads();
    if (tid < 32) {
        float v = (tid < 8) ? s_red[tid] : 0.0f;
        #pragma unroll
        for (int off = 4; off > 0; off >>= 1)
            v += __shfl_down_sync(0xFFFFFFFFu, v, off);
        if (tid == 0) {
            if (masked) {
                atomicAdd(&g_bsum[b], (double)(-v));
                atomicAdd(&g_bcnt[b], 1);
            }
            out[1 + 2 * NEL + row] = masked ? 1.0f : 0.0f;
            __threadfence();
            unsigned done = atomicAdd(&g_ticket, 1u);
            s_last = (done == (unsigned)(NROW - 1));
        }
    }
    __syncthreads();

    // ---- last block finalizes loss and resets scratch ----
    if (s_last) {
        __threadfence();   // see all other blocks' atomics
        const int c = g_bcnt[tid];
        s_d[tid] = (c > 0) ? (g_bsum[tid] / ((double)c * (double)QQ)) : 0.0;
        __syncthreads();
        #pragma unroll
        for (int off = BB / 2; off > 0; off >>= 1) {
            if (tid < off) s_d[tid] += s_d[tid + off];
            __syncthreads();
        }
        if (tid == 0) {
            out[0] = (float)s_d[0];
            g_ticket = 0u;
        }
        g_bsum[tid] = 0.0;
        g_bcnt[tid] = 0;
    }
}

extern "C" void kernel_launch(void* const* d_in, const int* in_sizes, int n_in,
                              void* d_out, int out_size) {
    const float* pred  = (const float*)d_in[0];
    const float* batch = (const float*)d_in[1];
    float* out = (float*)d_out;

    dim3 grid(TT, BB);
    row_kernel<<<grid, 256>>>(pred, batch, out);
}

// round 6
// speedup vs baseline: 1.0443x; 1.0443x over previous
#include <cuda_runtime.h>
#include <cstdint>

#define BB 256
#define TT 199
#define QQ 1000
#define NROW (BB * TT)               // 50,944
#define NEL  ((size_t)NROW * QQ)     // 50,944,000

// Scratch (__device__ global, no allocation)
__device__ float g_rowbce[NROW];

// ===== EXACT Round-2 hot-path kernel (117.5us, DRAM 82.1%) — unchanged =====
__global__ __launch_bounds__(256) void row_kernel(
    const float* __restrict__ pred,    // (B, T, Q)
    const float* __restrict__ batch,   // (B, T+1, Q)
    float* __restrict__ out)
{
    const int t   = blockIdx.x;
    const int b   = blockIdx.y;
    const int tid = threadIdx.x;
    const int lane = tid & 31;
    const int wid  = tid >> 5;

    const size_t row = (size_t)b * TT + t;
    const float* __restrict__ gt_row = batch + ((size_t)b * (TT + 1) + (t + 1)) * QQ;
    const float* __restrict__ p_row  = pred + row * QQ;

    __shared__ int   s_w[8];
    __shared__ float s_red[8];

    // Load everything up front, unconditionally (max MLP, no serialization).
    float g[4], p[4];
    #pragma unroll
    for (int k = 0; k < 4; k++) {
        int q = tid + 256 * k;
        bool valid = (k < 3) || (tid < QQ - 768);   // q < 1000
        g[k] = valid ? gt_row[q] : 0.0f;
        p[k] = valid ? p_row[q]  : 0.0f;
    }

    // Block-wide "any(g == 1)" via ballot + smem OR.
    int anyv = (g[0] == 1.0f) | (g[1] == 1.0f) | (g[2] == 1.0f) | (g[3] == 1.0f);
    unsigned wany = __ballot_sync(0xFFFFFFFFu, anyv);
    if (lane == 0) s_w[wid] = (wany != 0);
    __syncthreads();
    const int masked = s_w[0] | s_w[1] | s_w[2] | s_w[3] |
                       s_w[4] | s_w[5] | s_w[6] | s_w[7];
    const float fm = masked ? 1.0f : 0.0f;

    float* __restrict__ out_pred = out + 1 + row * QQ;
    float* __restrict__ out_gt   = out + 1 + NEL + row * QQ;

    float lsum = 0.0f;   // accumulates +(g*log p + (1-g)*log(1-p)); bce = -lsum
    #pragma unroll
    for (int k = 0; k < 4; k++) {
        int q = tid + 256 * k;
        bool valid = (k < 3) || (tid < QQ - 768);
        float pp = p[k], gg = g[k];
        float lp = fmaxf(__logf(pp),        -100.0f);
        float l1 = fmaxf(__logf(1.0f - pp), -100.0f);
        lsum += gg * lp + (1.0f - gg) * l1;
        if (valid) {
            out_pred[q] = pp * fm;
            out_gt[q]   = gg * fm;
        }
    }

    // Block reduction of lsum.
    #pragma unroll
    for (int off = 16; off > 0; off >>= 1)
        lsum += __shfl_down_sync(0xFFFFFFFFu, lsum, off);
    if (lane == 0) s_red[wid] = lsum;
    __syncthreads();
    if (tid < 32) {
        float v = (tid < 8) ? s_red[tid] : 0.0f;
        #pragma unroll
        for (int off = 4; off > 0; off >>= 1)
            v += __shfl_down_sync(0xFFFFFFFFu, v, off);
        if (tid == 0) {
            g_rowbce[row] = fm * (-v);
            out[1 + 2 * NEL + row] = fm;   // row_mask as float 0/1
        }
    }
}

// ===== Single combined finalize: 1 block, 1024 threads (32 warps).
// Warp w handles batches b = w, w+32, ... (8 jobs). Lanes stride the 199
// rows of a batch (coalesced over g_rowbce / mask, both L2-resident).
__global__ __launch_bounds__(1024) void final_kernel(float* __restrict__ out)
{
    const int tid  = threadIdx.x;
    const int lane = tid & 31;
    const int w    = tid >> 5;

    __shared__ double s_acc[32];

    const float* __restrict__ maskv = out + 1 + 2 * NEL;

    double acc = 0.0;
    #pragma unroll
    for (int j = 0; j < 8; j++) {
        const int b = w + 32 * j;
        const int base = b * TT;
        float sum = 0.0f;
        int   cnt = 0;
        #pragma unroll
        for (int it = 0; it < 7; it++) {
            int t = lane + 32 * it;
            if (t < TT) {
                sum += g_rowbce[base + t];
                cnt += (int)maskv[base + t];
            }
        }
        #pragma unroll
        for (int off = 16; off > 0; off >>= 1) {
            sum += __shfl_down_sync(0xFFFFFFFFu, sum, off);
            cnt += __shfl_down_sync(0xFFFFFFFFu, cnt, off);
        }
        if (lane == 0 && cnt > 0)
            acc += (double)sum / ((double)cnt * (double)QQ);
    }
    if (lane == 0) s_acc[w] = acc;
    __syncthreads();
    if (w == 0) {
        double v = s_acc[lane];
        #pragma unroll
        for (int off = 16; off > 0; off >>= 1)
            v += __shfl_down_sync(0xFFFFFFFFu, v, off);
        if (lane == 0) out[0] = (float)v;
    }
}

extern "C" void kernel_launch(void* const* d_in, const int* in_sizes, int n_in,
                              void* d_out, int out_size) {
    const float* pred  = (const float*)d_in[0];
    const float* batch = (const float*)d_in[1];
    float* out = (float*)d_out;

    dim3 grid(TT, BB);
    row_kernel<<<grid, 256>>>(pred, batch, out);
    final_kernel<<<1, 1024>>>(out);
}

// round 7
// speedup vs baseline: 1.2545x; 1.2013x over previous
#include <cuda_runtime.h>
#include <cstdint>

#define BB 256
#define TT 199
#define QQ 1000
#define NROW (BB * TT)               // 50,944
#define NEL  ((size_t)NROW * QQ)     // 50,944,000

// Scratch (__device__ global, no allocation)
__device__ float g_rowbce[NROW];

// ===== EXACT Round-2 hot-path kernel (117.5us, DRAM 82.1%) — unchanged
// except one idle-thread write zeroing out[0] for the finalize atomics. =====
__global__ __launch_bounds__(256) void row_kernel(
    const float* __restrict__ pred,    // (B, T, Q)
    const float* __restrict__ batch,   // (B, T+1, Q)
    float* __restrict__ out)
{
    const int t   = blockIdx.x;
    const int b   = blockIdx.y;
    const int tid = threadIdx.x;
    const int lane = tid & 31;
    const int wid  = tid >> 5;

    const size_t row = (size_t)b * TT + t;
    const float* __restrict__ gt_row = batch + ((size_t)b * (TT + 1) + (t + 1)) * QQ;
    const float* __restrict__ p_row  = pred + row * QQ;

    __shared__ int   s_w[8];
    __shared__ float s_red[8];

    // Load everything up front, unconditionally (max MLP, no serialization).
    float g[4], p[4];
    #pragma unroll
    for (int k = 0; k < 4; k++) {
        int q = tid + 256 * k;
        bool valid = (k < 3) || (tid < QQ - 768);   // q < 1000
        g[k] = valid ? gt_row[q] : 0.0f;
        p[k] = valid ? p_row[q]  : 0.0f;
    }

    // Block-wide "any(g == 1)" via ballot + smem OR.
    int anyv = (g[0] == 1.0f) | (g[1] == 1.0f) | (g[2] == 1.0f) | (g[3] == 1.0f);
    unsigned wany = __ballot_sync(0xFFFFFFFFu, anyv);
    if (lane == 0) s_w[wid] = (wany != 0);
    __syncthreads();
    const int masked = s_w[0] | s_w[1] | s_w[2] | s_w[3] |
                       s_w[4] | s_w[5] | s_w[6] | s_w[7];
    const float fm = masked ? 1.0f : 0.0f;

    float* __restrict__ out_pred = out + 1 + row * QQ;
    float* __restrict__ out_gt   = out + 1 + NEL + row * QQ;

    float lsum = 0.0f;   // accumulates +(g*log p + (1-g)*log(1-p)); bce = -lsum
    #pragma unroll
    for (int k = 0; k < 4; k++) {
        int q = tid + 256 * k;
        bool valid = (k < 3) || (tid < QQ - 768);
        float pp = p[k], gg = g[k];
        float lp = fmaxf(__logf(pp),        -100.0f);
        float l1 = fmaxf(__logf(1.0f - pp), -100.0f);
        lsum += gg * lp + (1.0f - gg) * l1;
        if (valid) {
            out_pred[q] = pp * fm;
            out_gt[q]   = gg * fm;
        }
    }

    // Block reduction of lsum.
    #pragma unroll
    for (int off = 16; off > 0; off >>= 1)
        lsum += __shfl_down_sync(0xFFFFFFFFu, lsum, off);
    if (lane == 0) s_red[wid] = lsum;
    __syncthreads();
    if (tid < 32) {
        float v = (tid < 8) ? s_red[tid] : 0.0f;
        #pragma unroll
        for (int off = 4; off > 0; off >>= 1)
            v += __shfl_down_sync(0xFFFFFFFFu, v, off);
        if (tid == 0) {
            g_rowbce[row] = fm * (-v);
            out[1 + 2 * NEL + row] = fm;   // row_mask as float 0/1
        }
    } else if (tid == 255 && t == 0 && b == 0) {
        out[0] = 0.0f;                     // base for finalize atomics
    }
}

// ===== Single parallel finalize: one block per batch (256 blocks, 224 thr).
// Thread t reads g_rowbce[b*TT + t] (coalesced, L2-resident). A masked row
// always has bce >= ~10 (each element adds >= -log(0.99)), so mask == (bce != 0).
__global__ __launch_bounds__(224) void final_kernel(float* __restrict__ out)
{
    const int b    = blockIdx.x;
    const int tid  = threadIdx.x;
    const int lane = tid & 31;
    const int w    = tid >> 5;

    __shared__ float s_s[7];
    __shared__ int   s_c[7];

    float v = 0.0f;
    int   c = 0;
    if (tid < TT) {
        v = g_rowbce[b * TT + tid];
        c = (v != 0.0f);
    }
    #pragma unroll
    for (int off = 16; off > 0; off >>= 1) {
        v += __shfl_down_sync(0xFFFFFFFFu, v, off);
        c += __shfl_down_sync(0xFFFFFFFFu, c, off);
    }
    if (lane == 0) { s_s[w] = v; s_c[w] = c; }
    __syncthreads();
    if (tid == 0) {
        float sum = 0.0f; int cnt = 0;
        #pragma unroll
        for (int i = 0; i < 7; i++) { sum += s_s[i]; cnt += s_c[i]; }
        if (cnt > 0)
            atomicAdd(out, (float)((double)sum / ((double)cnt * (double)QQ)));
    }
}

extern "C" void kernel_launch(void* const* d_in, const int* in_sizes, int n_in,
                              void* d_out, int out_size) {
    const float* pred  = (const float*)d_in[0];
    const float* batch = (const float*)d_in[1];
    float* out = (float*)d_out;

    dim3 grid(TT, BB);
    row_kernel<<<grid, 256>>>(pred, batch, out);
    final_kernel<<<BB, 224>>>(out);
}

// round 8
// speedup vs baseline: 1.2564x; 1.0015x over previous
#include <cuda_runtime.h>
#include <cstdint>

#define BB 256
#define TT 199
#define QQ 1000
#define NROW (BB * TT)               // 50,944
#define NEL  ((size_t)NROW * QQ)     // 50,944,000

// Scratch (__device__ global, no allocation)
__device__ float g_rowbce[NROW];

// ===== Proven hot-path kernel (117.5us, DRAM 82.1%) — body unchanged;
// adds only the PDL trigger at the very end. =====
__global__ __launch_bounds__(256) void row_kernel(
    const float* __restrict__ pred,    // (B, T, Q)
    const float* __restrict__ batch,   // (B, T+1, Q)
    float* __restrict__ out)
{
    const int t   = blockIdx.x;
    const int b   = blockIdx.y;
    const int tid = threadIdx.x;
    const int lane = tid & 31;
    const int wid  = tid >> 5;

    const size_t row = (size_t)b * TT + t;
    const float* __restrict__ gt_row = batch + ((size_t)b * (TT + 1) + (t + 1)) * QQ;
    const float* __restrict__ p_row  = pred + row * QQ;

    __shared__ int   s_w[8];
    __shared__ float s_red[8];

    // Load everything up front, unconditionally (max MLP, no serialization).
    float g[4], p[4];
    #pragma unroll
    for (int k = 0; k < 4; k++) {
        int q = tid + 256 * k;
        bool valid = (k < 3) || (tid < QQ - 768);   // q < 1000
        g[k] = valid ? gt_row[q] : 0.0f;
        p[k] = valid ? p_row[q]  : 0.0f;
    }

    // Block-wide "any(g == 1)" via ballot + smem OR.
    int anyv = (g[0] == 1.0f) | (g[1] == 1.0f) | (g[2] == 1.0f) | (g[3] == 1.0f);
    unsigned wany = __ballot_sync(0xFFFFFFFFu, anyv);
    if (lane == 0) s_w[wid] = (wany != 0);
    __syncthreads();
    const int masked = s_w[0] | s_w[1] | s_w[2] | s_w[3] |
                       s_w[4] | s_w[5] | s_w[6] | s_w[7];
    const float fm = masked ? 1.0f : 0.0f;

    float* __restrict__ out_pred = out + 1 + row * QQ;
    float* __restrict__ out_gt   = out + 1 + NEL + row * QQ;

    float lsum = 0.0f;   // accumulates +(g*log p + (1-g)*log(1-p)); bce = -lsum
    #pragma unroll
    for (int k = 0; k < 4; k++) {
        int q = tid + 256 * k;
        bool valid = (k < 3) || (tid < QQ - 768);
        float pp = p[k], gg = g[k];
        float lp = fmaxf(__logf(pp),        -100.0f);
        float l1 = fmaxf(__logf(1.0f - pp), -100.0f);
        lsum += gg * lp + (1.0f - gg) * l1;
        if (valid) {
            out_pred[q] = pp * fm;
            out_gt[q]   = gg * fm;
        }
    }

    // Block reduction of lsum.
    #pragma unroll
    for (int off = 16; off > 0; off >>= 1)
        lsum += __shfl_down_sync(0xFFFFFFFFu, lsum, off);
    if (lane == 0) s_red[wid] = lsum;
    __syncthreads();
    if (tid < 32) {
        float v = (tid < 8) ? s_red[tid] : 0.0f;
        #pragma unroll
        for (int off = 4; off > 0; off >>= 1)
            v += __shfl_down_sync(0xFFFFFFFFu, v, off);
        if (tid == 0) {
            g_rowbce[row] = fm * (-v);
            out[1 + 2 * NEL + row] = fm;   // row_mask as float 0/1
        }
    } else if (tid == 255 && t == 0 && b == 0) {
        out[0] = 0.0f;                     // base for finalize atomics
    }

    // PDL: allow the dependent finalize grid to begin launching now.
    cudaTriggerProgrammaticLaunchCompletion();
}

// ===== Parallel finalize: one block per batch. Launched with PDL so its
// launch latency overlaps row_kernel's tail; the grid-dependency sync below
// guarantees all g_rowbce / mask writes are visible before any read. =====
__global__ __launch_bounds__(224) void final_kernel(float* __restrict__ out)
{
    const int b    = blockIdx.x;
    const int tid  = threadIdx.x;
    const int lane = tid & 31;
    const int w    = tid >> 5;

    __shared__ float s_s[7];
    __shared__ int   s_c[7];

    cudaGridDependencySynchronize();   // wait for row_kernel completion

    float v = 0.0f;
    int   c = 0;
    if (tid < TT) {
        v = g_rowbce[b * TT + tid];
        c = (v != 0.0f);   // masked row => bce >= ~10; unmasked => exactly 0
    }
    #pragma unroll
    for (int off = 16; off > 0; off >>= 1) {
        v += __shfl_down_sync(0xFFFFFFFFu, v, off);
        c += __shfl_down_sync(0xFFFFFFFFu, c, off);
    }
    if (lane == 0) { s_s[w] = v; s_c[w] = c; }
    __syncthreads();
    if (tid == 0) {
        float sum = 0.0f; int cnt = 0;
        #pragma unroll
        for (int i = 0; i < 7; i++) { sum += s_s[i]; cnt += s_c[i]; }
        if (cnt > 0)
            atomicAdd(out, (float)((double)sum / ((double)cnt * (double)QQ)));
    }
}

extern "C" void kernel_launch(void* const* d_in, const int* in_sizes, int n_in,
                              void* d_out, int out_size) {
    const float* pred  = (const float*)d_in[0];
    const float* batch = (const float*)d_in[1];
    float* out = (float*)d_out;

    dim3 grid(TT, BB);
    row_kernel<<<grid, 256>>>(pred, batch, out);

    // Finalize with programmatic dependent launch (overlaps launch latency
    // with row_kernel's tail; capturable into the graph).
    cudaLaunchConfig_t cfg = {};
    cfg.gridDim  = dim3(BB, 1, 1);
    cfg.blockDim = dim3(224, 1, 1);
    cfg.dynamicSmemBytes = 0;
    cfg.stream = 0;
    cudaLaunchAttribute attr[1];
    attr[0].id = cudaLaunchAttributeProgrammaticStreamSerialization;
    attr[0].val.programmaticStreamSerializationAllowed = 1;
    cfg.attrs = attr;
    cfg.numAttrs = 1;
    cudaLaunchKernelEx(&cfg, final_kernel, out);
}